// round 4
// baseline (speedup 1.0000x reference)
#include <cuda_runtime.h>
#include <math.h>

#define NATOMS 256
#define RCR 5.2f
#define RCA 3.5f
#define PI_F 3.14159265358979323846f
#define CAP_R 96   // radial neighbors (mean ~19)
#define CAP_A 48   // angular neighbors (mean ~5.7)
#define FULL 0xFFFFFFFFu
#define TPB 128    // 4 warps per atom
#define NREP (NATOMS / TPB)   // 2

__global__ void __launch_bounds__(TPB) aev_kernel(
    const float* __restrict__ coords,
    const float* __restrict__ charges,
    float* __restrict__ out)
{
    __shared__ float rd[CAP_R], rw[CAP_R];                    // radial: dist, 0.25*fc*q
    __shared__ float adx[CAP_A], ady[CAP_A], adz[CAP_A];      // angular: i->j vector
    __shared__ float ad[CAP_A], afq[CAP_A];                   // dist, fc*q
    __shared__ int   wcR[NREP * 4], wcA[NREP * 4];            // per (rep,warp) counts
    __shared__ float rpart[4][16], apart[4][32];

    const int i    = blockIdx.x;
    const int tid  = threadIdx.x;
    const int w    = tid >> 5;
    const int lane = tid & 31;
    const unsigned below = (1u << lane) - 1u;

    const float xi = __ldg(&coords[i * 3 + 0]);
    const float yi = __ldg(&coords[i * 3 + 1]);
    const float zi = __ldg(&coords[i * 3 + 2]);

    // ---------- pass 1: distances + ballots (deterministic ordering) ----------
    float dxv[NREP], dyv[NREP], dzv[NREP], dv[NREP], qv[NREP];
    unsigned mRv[NREP], mAv[NREP];
    bool inRv[NREP], inAv[NREP];

    #pragma unroll
    for (int rep = 0; rep < NREP; rep++) {
        const int j = rep * TPB + tid;
        const float dx = __ldg(&coords[j * 3 + 0]) - xi;
        const float dy = __ldg(&coords[j * 3 + 1]) - yi;
        const float dz = __ldg(&coords[j * 3 + 2]) - zi;
        const float d  = sqrtf(dx * dx + dy * dy + dz * dz);
        const bool ok  = (j != i);
        const bool inR = ok && (d < RCR);
        const bool inA = ok && (d < RCA);
        dxv[rep] = dx; dyv[rep] = dy; dzv[rep] = dz; dv[rep] = d;
        qv[rep]  = __ldg(&charges[j]);
        inRv[rep] = inR; inAv[rep] = inA;
        mRv[rep] = __ballot_sync(FULL, inR);
        mAv[rep] = __ballot_sync(FULL, inA);
        if (lane == 0) {
            wcR[rep * 4 + w] = __popc(mRv[rep]);
            wcA[rep * 4 + w] = __popc(mAv[rep]);
        }
    }
    __syncthreads();

    // ---------- pass 2: exclusive-prefix bases + compacted writes ----------
    #pragma unroll
    for (int rep = 0; rep < NREP; rep++) {
        const int seg = rep * 4 + w;
        int baseR = 0, baseA = 0;
        for (int k = 0; k < seg; k++) { baseR += wcR[k]; baseA += wcA[k]; }
        if (inRv[rep]) {
            const int s = baseR + __popc(mRv[rep] & below);
            const float d = dv[rep];
            const float fc = 0.5f * __cosf((PI_F / RCR) * d) + 0.5f;
            rd[s] = d; rw[s] = 0.25f * fc * qv[rep];
        }
        if (inAv[rep]) {
            const int s = baseA + __popc(mAv[rep] & below);
            const float d = dv[rep];
            const float fc = 0.5f * __cosf((PI_F / RCA) * d) + 0.5f;
            adx[s] = dxv[rep]; ady[s] = dyv[rep]; adz[s] = dzv[rep];
            ad[s] = d; afq[s] = fc * qv[rep];
        }
    }
    __syncthreads();

    int NR = 0, NA = 0;
    #pragma unroll
    for (int k = 0; k < NREP * 4; k++) { NR += wcR[k]; NA += wcA[k]; }

    // ---------- radial: lane (l&15) <-> shift m; two neighbors per warp iter ----------
    {
        const int   m   = lane & 15;
        const int   hlf = lane >> 4;
        const float sh  = 0.9f + 0.26875f * (float)m;
        float acc = 0.0f;
        for (int t = w * 2 + hlf; t < NR; t += 8) {
            const float u = rd[t] - sh;          // rd[t]: 2-addr broadcast LDS
            acc += rw[t] * __expf(-16.0f * u * u);
        }
        acc += __shfl_xor_sync(FULL, acc, 16);   // fold the two half-warp neighbor sets
        if (lane < 16) rpart[w][lane] = acc;
    }

    // ---------- angular: warp cooperates per pair; lane <-> (az,zz) slot ----------
    {
        const int   azi  = lane >> 3;
        const int   zz   = lane & 7;
        const float sha  = 0.9f + 0.65f * (float)azi;
        const float angl = PI_F / 16.0f + (PI_F / 8.0f) * (float)zz;
        const float cz   = __cosf(angl);
        const float sz   = __sinf(angl);
        float acc = 0.0f;

        int p = 0;
        for (int a = 0; a < NA; a++) {
            const float ax = adx[a], ay = ady[a], avz = adz[a];
            const float da = ad[a], fqa = afq[a];
            for (int b = a + 1; b < NA; b++, p++) {
                if ((p & 3) != w) continue;      // round-robin pairs over 4 warps
                const float dot = ax * adx[b] + ay * ady[b] + avz * adz[b];
                const float db  = ad[b];
                const float cth = 0.95f * __fdividef(dot, da * db);
                const float sth = sqrtf(fmaxf(1.0f - cth * cth, 0.0f));
                const float wgt = 2.0f * fqa * afq[b];
                const float davg = 0.5f * (da + db);
                const float u   = davg - sha;
                const float rad = wgt * __expf(-8.0f * u * u);
                // cos(theta - ShfZ) = cth*cos(ShfZ) + sin(theta)*sin(ShfZ)  (exact)
                const float x   = 0.5f * (1.0f + cth * cz + sth * sz);
                const float x2  = x * x;
                const float x4  = x2 * x2;
                const float x8  = x4 * x4;
                const float x16 = x8 * x8;
                acc += rad * (x16 * x16);
            }
        }
        apart[w][lane] = acc;
    }
    __syncthreads();

    // ---------- combine 4 warp partials, write [48] ----------
    if (tid < 48) {
        float v;
        if (tid < 16)
            v = rpart[0][tid] + rpart[1][tid] + rpart[2][tid] + rpart[3][tid];
        else {
            const int s = tid - 16;
            v = apart[0][s] + apart[1][s] + apart[2][s] + apart[3][s];
        }
        out[i * 48 + tid] = v;
    }
}

extern "C" void kernel_launch(void* const* d_in, const int* in_sizes, int n_in,
                              void* d_out, int out_size) {
    const float* coords  = (const float*)d_in[0];  // [256,3] fp32
    const float* charges = (const float*)d_in[1];  // [256]   fp32
    float* out = (float*)d_out;                    // [256,48] fp32
    aev_kernel<<<NATOMS, TPB>>>(coords, charges, out);
}

// round 5
// speedup vs baseline: 1.5156x; 1.5156x over previous
#include <cuda_runtime.h>
#include <math.h>

#define NATOMS 256
#define RCR 5.2f
#define RCA 3.5f
#define PI_F 3.14159265358979323846f
#define CAP_R 96   // radial neighbors (mean ~19)
#define CAP_A 48   // angular neighbors (mean ~5.7)
#define FULL 0xFFFFFFFFu
#define TPB 128    // 4 warps per atom
#define NREP (NATOMS / TPB)   // 2

__global__ void __launch_bounds__(TPB) aev_kernel(
    const float* __restrict__ coords,
    const float* __restrict__ charges,
    float* __restrict__ out)
{
    __shared__ float rd[CAP_R], rw[CAP_R];                    // radial: dist, 0.25*fc*q
    __shared__ float adx[CAP_A], ady[CAP_A], adz[CAP_A];      // angular: i->j vector
    __shared__ float ad[CAP_A], afq[CAP_A];                   // dist, fc*q
    __shared__ int   wcR[NREP * 4], wcA[NREP * 4];            // per (rep,warp) counts
    __shared__ float part[TPB][49];                           // padded transpose buffer

    const int i    = blockIdx.x;
    const int tid  = threadIdx.x;
    const int w    = tid >> 5;
    const int lane = tid & 31;
    const unsigned below = (1u << lane) - 1u;

    const float xi = __ldg(&coords[i * 3 + 0]);
    const float yi = __ldg(&coords[i * 3 + 1]);
    const float zi = __ldg(&coords[i * 3 + 2]);

    // ---------- pass 1: distances + ballots (deterministic ordering) ----------
    float dxv[NREP], dyv[NREP], dzv[NREP], dv[NREP], qv[NREP];
    unsigned mRv[NREP], mAv[NREP];
    bool inRv[NREP], inAv[NREP];

    #pragma unroll
    for (int rep = 0; rep < NREP; rep++) {
        const int j = rep * TPB + tid;
        const float dx = __ldg(&coords[j * 3 + 0]) - xi;
        const float dy = __ldg(&coords[j * 3 + 1]) - yi;
        const float dz = __ldg(&coords[j * 3 + 2]) - zi;
        const float d  = sqrtf(dx * dx + dy * dy + dz * dz);
        const bool ok  = (j != i);
        const bool inR = ok && (d < RCR);
        const bool inA = ok && (d < RCA);
        dxv[rep] = dx; dyv[rep] = dy; dzv[rep] = dz; dv[rep] = d;
        qv[rep]  = __ldg(&charges[j]);
        inRv[rep] = inR; inAv[rep] = inA;
        mRv[rep] = __ballot_sync(FULL, inR);
        mAv[rep] = __ballot_sync(FULL, inA);
        if (lane == 0) {
            wcR[rep * 4 + w] = __popc(mRv[rep]);
            wcA[rep * 4 + w] = __popc(mAv[rep]);
        }
    }
    __syncthreads();

    // ---------- pass 2: exclusive-prefix bases + compacted writes ----------
    #pragma unroll
    for (int rep = 0; rep < NREP; rep++) {
        const int seg = rep * 4 + w;
        int baseR = 0, baseA = 0;
        #pragma unroll
        for (int k = 0; k < NREP * 4; k++) {
            if (k < seg) { baseR += wcR[k]; baseA += wcA[k]; }
        }
        if (inRv[rep]) {
            const int s = baseR + __popc(mRv[rep] & below);
            const float d = dv[rep];
            const float fc = 0.5f * __cosf((PI_F / RCR) * d) + 0.5f;
            rd[s] = d; rw[s] = 0.25f * fc * qv[rep];
        }
        if (inAv[rep]) {
            const int s = baseA + __popc(mAv[rep] & below);
            const float d = dv[rep];
            const float fc = 0.5f * __cosf((PI_F / RCA) * d) + 0.5f;
            adx[s] = dxv[rep]; ady[s] = dyv[rep]; adz[s] = dzv[rep];
            ad[s] = d; afq[s] = fc * qv[rep];
        }
    }
    __syncthreads();

    int NR = 0, NA = 0;
    #pragma unroll
    for (int k = 0; k < NREP * 4; k++) { NR += wcR[k]; NA += wcA[k]; }

    // ---------- radial: neighbor-per-lane, 16 slots serial (high ILP) ----------
    float accR[16];
    #pragma unroll
    for (int m = 0; m < 16; m++) accR[m] = 0.0f;

    for (int t = tid; t < NR; t += TPB) {
        const float d = rd[t];
        const float wq = rw[t];
        #pragma unroll
        for (int m = 0; m < 16; m++) {
            const float sh = 0.9f + 0.26875f * (float)m;
            const float u  = d - sh;
            accR[m] += wq * __expf(-16.0f * u * u);
        }
    }

    // ---------- angular: pair-per-lane, 32 slots serial (high ILP) ----------
    float accA[32];
    #pragma unroll
    for (int s = 0; s < 32; s++) accA[s] = 0.0f;

    const int M = NA;
    for (int p = tid; p < M * M; p += TPB) {
        const int a = p / M;
        const int b = p % M;
        if (a >= b) continue;  // unordered pairs; reference double-counts ordered -> x2

        const float da = ad[a], db = ad[b];
        const float dot = adx[a] * adx[b] + ady[a] * ady[b] + adz[a] * adz[b];
        const float cth = 0.95f * __fdividef(dot, da * db);      // |cth| <= 0.95
        const float sth = sqrtf(fmaxf(1.0f - cth * cth, 0.0f));  // theta in [0,pi]
        const float wgt = 2.0f * afq[a] * afq[b];
        const float davg = 0.5f * (da + db);

        #pragma unroll
        for (int az = 0; az < 4; az++) {
            const float sha = 0.9f + 0.65f * (float)az;
            const float u   = davg - sha;
            const float rad = wgt * __expf(-8.0f * u * u);
            #pragma unroll
            for (int zz = 0; zz < 8; zz++) {
                const float ang = PI_F / 16.0f + (PI_F / 8.0f) * (float)zz;
                const float cz  = cosf(ang);   // compile-time constants
                const float sz  = sinf(ang);
                // cos(theta - ShfZ) = cth*cos(ShfZ) + sin(theta)*sin(ShfZ)  (exact)
                const float x   = 0.5f * (1.0f + cth * cz + sth * sz);
                const float x2  = x * x;
                const float x4  = x2 * x2;
                const float x8  = x4 * x4;
                const float x16 = x8 * x8;
                accA[az * 8 + zz] += rad * (x16 * x16);
            }
        }
    }

    // ---------- shared transpose reduction (no shuffles) ----------
    #pragma unroll
    for (int m = 0; m < 16; m++) part[tid][m] = accR[m];
    #pragma unroll
    for (int s = 0; s < 32; s++) part[tid][16 + s] = accA[s];
    __syncthreads();

    if (tid < 48) {
        float v = 0.0f;
        #pragma unroll
        for (int l = 0; l < TPB; l++) v += part[l][tid];
        out[i * 48 + tid] = v;
    }
}

extern "C" void kernel_launch(void* const* d_in, const int* in_sizes, int n_in,
                              void* d_out, int out_size) {
    const float* coords  = (const float*)d_in[0];  // [256,3] fp32
    const float* charges = (const float*)d_in[1];  // [256]   fp32
    float* out = (float*)d_out;                    // [256,48] fp32
    aev_kernel<<<NATOMS, TPB>>>(coords, charges, out);
}

// round 6
// speedup vs baseline: 1.7399x; 1.1480x over previous
#include <cuda_runtime.h>
#include <math.h>

#define NATOMS 256
#define RCR 5.2f
#define RCA 3.5f
#define PI_F 3.14159265358979323846f
#define CAP_A 48   // angular neighbors (mean ~5.7)
#define FULL 0xFFFFFFFFu
#define TPB 128    // 4 warps per atom
#define NREP (NATOMS / TPB)   // 2

__global__ void __launch_bounds__(TPB) aev_kernel(
    const float* __restrict__ coords,
    const float* __restrict__ charges,
    float* __restrict__ out)
{
    __shared__ float adx[CAP_A], ady[CAP_A], adz[CAP_A];      // angular: i->j vector
    __shared__ float ad[CAP_A], afq[CAP_A];                   // dist, fc*q
    __shared__ int   wcA[NREP * 4];                           // per (rep,warp) angular counts
    __shared__ float part[TPB][49];                           // padded transpose buffer

    const int i    = blockIdx.x;
    const int tid  = threadIdx.x;
    const int w    = tid >> 5;
    const int lane = tid & 31;
    const unsigned below = (1u << lane) - 1u;

    const float xi = __ldg(&coords[i * 3 + 0]);
    const float yi = __ldg(&coords[i * 3 + 1]);
    const float zi = __ldg(&coords[i * 3 + 2]);

    float accR[16];
    #pragma unroll
    for (int m = 0; m < 16; m++) accR[m] = 0.0f;

    // ---------- pass 1: distances, radial-direct accumulation, angular ballots ----------
    float dxv[NREP], dyv[NREP], dzv[NREP], dv[NREP], qv[NREP];
    unsigned mAv[NREP];
    bool inAv[NREP];

    #pragma unroll
    for (int rep = 0; rep < NREP; rep++) {
        const int j = rep * TPB + tid;
        const float dx = __ldg(&coords[j * 3 + 0]) - xi;
        const float dy = __ldg(&coords[j * 3 + 1]) - yi;
        const float dz = __ldg(&coords[j * 3 + 2]) - zi;
        const float d  = sqrtf(dx * dx + dy * dy + dz * dz);
        const float q  = __ldg(&charges[j]);
        const bool ok  = (j != i);
        const bool inR = ok && (d < RCR);
        const bool inA = ok && (d < RCA);
        dxv[rep] = dx; dyv[rep] = dy; dzv[rep] = dz; dv[rep] = d; qv[rep] = q;
        inAv[rep] = inA;
        mAv[rep]  = __ballot_sync(FULL, inA);
        if (lane == 0) wcA[rep * 4 + w] = __popc(mAv[rep]);

        // radial: accumulate directly (no list) — predicated by cutoff
        if (inR) {
            const float fc = 0.5f * __cosf((PI_F / RCR) * d) + 0.5f;
            const float wq = 0.25f * fc * q;
            #pragma unroll
            for (int m = 0; m < 16; m++) {
                const float sh = 0.9f + 0.26875f * (float)m;
                const float u  = d - sh;
                accR[m] += wq * __expf(-16.0f * u * u);
            }
        }
    }
    __syncthreads();

    // ---------- pass 2: deterministic compaction of angular list ----------
    #pragma unroll
    for (int rep = 0; rep < NREP; rep++) {
        const int seg = rep * 4 + w;
        int baseA = 0;
        #pragma unroll
        for (int k = 0; k < NREP * 4; k++)
            if (k < seg) baseA += wcA[k];
        if (inAv[rep]) {
            const int s = baseA + __popc(mAv[rep] & below);
            const float d = dv[rep];
            const float fc = 0.5f * __cosf((PI_F / RCA) * d) + 0.5f;
            adx[s] = dxv[rep]; ady[s] = dyv[rep]; adz[s] = dzv[rep];
            ad[s] = d; afq[s] = fc * qv[rep];
        }
    }
    __syncthreads();

    int NA = 0;
    #pragma unroll
    for (int k = 0; k < NREP * 4; k++) NA += wcA[k];

    // ---------- angular: pair-per-lane, 32 slots serial (high ILP) ----------
    float accA[32];
    #pragma unroll
    for (int s = 0; s < 32; s++) accA[s] = 0.0f;

    const int M = NA;
    const float fM = (float)M;
    for (int p = tid; p < M * M; p += TPB) {
        // exact for p < 2^12, M >= 2: err 1/M >> ulp
        const int a = (int)(__fdividef((float)p, fM));
        const int b = p - a * M;
        if (a >= b) continue;  // unordered pairs; reference double-counts ordered -> x2

        const float da = ad[a], db = ad[b];
        const float dot = adx[a] * adx[b] + ady[a] * ady[b] + adz[a] * adz[b];
        const float cth = 0.95f * __fdividef(dot, da * db);      // |cth| <= 0.95
        const float sth = sqrtf(fmaxf(1.0f - cth * cth, 0.0f));  // theta in [0,pi]
        const float wgt = 2.0f * afq[a] * afq[b];
        const float davg = 0.5f * (da + db);

        #pragma unroll
        for (int az = 0; az < 4; az++) {
            const float sha = 0.9f + 0.65f * (float)az;
            const float u   = davg - sha;
            const float rad = wgt * __expf(-8.0f * u * u);
            #pragma unroll
            for (int zz = 0; zz < 8; zz++) {
                const float ang = PI_F / 16.0f + (PI_F / 8.0f) * (float)zz;
                const float cz  = cosf(ang);   // compile-time constants
                const float sz  = sinf(ang);
                // cos(theta - ShfZ) = cth*cos(ShfZ) + sin(theta)*sin(ShfZ)  (exact)
                const float x   = 0.5f * (1.0f + cth * cz + sth * sz);
                const float x2  = x * x;
                const float x4  = x2 * x2;
                const float x8  = x4 * x4;
                const float x16 = x8 * x8;
                accA[az * 8 + zz] += rad * (x16 * x16);
            }
        }
    }

    // ---------- shared transpose + 8-way-ILP column sum ----------
    #pragma unroll
    for (int m = 0; m < 16; m++) part[tid][m] = accR[m];
    #pragma unroll
    for (int s = 0; s < 32; s++) part[tid][16 + s] = accA[s];
    __syncthreads();

    if (tid < 48) {
        float v0 = 0.f, v1 = 0.f, v2 = 0.f, v3 = 0.f;
        float v4 = 0.f, v5 = 0.f, v6 = 0.f, v7 = 0.f;
        #pragma unroll
        for (int l = 0; l < TPB; l += 8) {
            v0 += part[l + 0][tid];
            v1 += part[l + 1][tid];
            v2 += part[l + 2][tid];
            v3 += part[l + 3][tid];
            v4 += part[l + 4][tid];
            v5 += part[l + 5][tid];
            v6 += part[l + 6][tid];
            v7 += part[l + 7][tid];
        }
        out[i * 48 + tid] = ((v0 + v1) + (v2 + v3)) + ((v4 + v5) + (v6 + v7));
    }
}

extern "C" void kernel_launch(void* const* d_in, const int* in_sizes, int n_in,
                              void* d_out, int out_size) {
    const float* coords  = (const float*)d_in[0];  // [256,3] fp32
    const float* charges = (const float*)d_in[1];  // [256]   fp32
    float* out = (float*)d_out;                    // [256,48] fp32
    aev_kernel<<<NATOMS, TPB>>>(coords, charges, out);
}